// round 5
// baseline (speedup 1.0000x reference)
#include <cuda_runtime.h>
#include <cuda_bf16.h>
#include <math.h>
#include <stdint.h>

// ---------------- problem constants ----------------
#define DM    1024          // d_model
#define DI    2048          // d_inner
#define DS    16            // d_state
#define RK    64            // dt_rank
#define BSZ   2
#define LSEQ  2048
#define TT    (BSZ*LSEQ)    // 4096 tokens
#define XZLD  (2*DI)        // 4096, xz row stride
#define XDBL_LD 96          // dt_rank + 2*d_state

// ---------------- scratch (static device memory; no allocs allowed) ------
__device__ __nv_bfloat16 g_xn_bf [TT*DM];       // 8 MB  layernorm output (bf16)
__device__ float         g_xz    [TT*XZLD];     // 64 MB in_proj output (x | z)
__device__ float         g_xc    [TT*DI];       // 32 MB conv+silu output (fp32 for scan)
__device__ __nv_bfloat16 g_xc_bf [TT*DI];       // 16 MB conv+silu output (bf16 for x_proj)
__device__ float         g_xdbl  [TT*XDBL_LD];  // 1.5 MB x_proj output (fp32 B | C in cols 64..95)
__device__ __nv_bfloat16 g_xdt_bf[TT*RK];       // 512KB x_proj dt-rank cols (bf16 for dt_proj)
__device__ float         g_dt    [TT*DI];       // 32 MB softplus(dt)
__device__ __nv_bfloat16 g_y_bf  [TT*DI];       // 16 MB scan output (gated, bf16)
__device__ __nv_bfloat16 g_win_bf [XZLD*DM];    // 8 MB  in_proj_w bf16
__device__ __nv_bfloat16 g_wout_bf[DM*DI];      // 4 MB  out_proj_w bf16
__device__ __nv_bfloat16 g_wxp_bf [128*DI];     // 512KB x_proj_w bf16, padded 96->128 rows
__device__ __nv_bfloat16 g_wdt_bf [DI*RK];      // 256KB dt_proj_w bf16

// ---------------- helpers ----------------
__device__ __forceinline__ float siluf(float v) {
    return v * __fdividef(1.f, 1.f + __expf(-v));
}

__device__ __forceinline__ uint32_t smem_u32(const void* p) {
    uint32_t a;
    asm("{ .reg .u64 t; cvta.to.shared.u64 t, %1; cvt.u32.u64 %0, t; }" : "=r"(a) : "l"(p));
    return a;
}

#define CP16(dst, src) \
    asm volatile("cp.async.cg.shared.global [%0], [%1], 16;" :: "r"(dst), "l"(src))
#define CP_COMMIT() asm volatile("cp.async.commit_group;")
#define CP_WAIT1()  asm volatile("cp.async.wait_group 1;")
#define CP_WAIT0()  asm volatile("cp.async.wait_group 0;")

#define LDSM_X4(r0, r1, r2, r3, addr) \
    asm volatile("ldmatrix.sync.aligned.m8n8.x4.shared.b16 {%0,%1,%2,%3}, [%4];" \
        : "=r"(r0), "=r"(r1), "=r"(r2), "=r"(r3) : "r"(addr))

#define MMA16816(d, a, b) \
    asm volatile("mma.sync.aligned.m16n8k16.row.col.f32.bf16.bf16.f32 " \
        "{%0,%1,%2,%3}, {%4,%5,%6,%7}, {%8,%9}, {%0,%1,%2,%3};" \
        : "+f"((d)[0]), "+f"((d)[1]), "+f"((d)[2]), "+f"((d)[3]) \
        : "r"((a)[0]), "r"((a)[1]), "r"((a)[2]), "r"((a)[3]), \
          "r"((b)[0]), "r"((b)[1]))

// ================== bf16 HMMA GEMM: C[m][n] = sum_k A[m][k]*B[n][k] =======
// CTA tile 128x128, BK=32, 256 threads (8 warps, 2x4 -> warp tile 64x32).
// SMEM rows padded to 80B pitch -> ldmatrix conflict-free. cp.async double buf.
// EPI: 0 = plain fp32 store
//      1 = softplus(acc + bias[n]) fp32 store
//      2 = resid + rs*acc
//      3 = cols<64 -> bf16 to xdt (ld 64); cols 64..95 -> fp32 to C
#define PITCH 80
#define ABUF  10240                 // 128 rows * 80B
#define SOFF_B (2*ABUF)

template<int EPI>
__global__ __launch_bounds__(256) void hgemm(
    const __nv_bfloat16* __restrict__ A, int lda,
    const __nv_bfloat16* __restrict__ B, int ldb,
    int K, float* __restrict__ C, int ldc, int Nreal,
    const float* __restrict__ aux,          // bias (EPI1) or resid (EPI2)
    const float* __restrict__ rs_ptr,
    __nv_bfloat16* __restrict__ xdt)        // EPI3 bf16 output
{
    __shared__ __align__(128) char sm[4*ABUF];   // A0 A1 B0 B1
    const int tid  = threadIdx.x;
    const int lane = tid & 31;
    const int w    = tid >> 5;
    const int wm   = w >> 2;        // 0..1
    const int wn   = w & 3;         // 0..3
    const int m0 = blockIdx.y * 128, n0 = blockIdx.x * 128;
    const uint32_t sbase = smem_u32(sm);

    float acc[4][4][4];
    #pragma unroll
    for (int i = 0; i < 4; i++)
        #pragma unroll
        for (int j = 0; j < 4; j++)
            #pragma unroll
            for (int q = 0; q < 4; q++) acc[i][j][q] = 0.f;

    // gmem->smem: 512 16B chunks per operand; thread handles chunks tid, tid+256
    const int r0c = tid >> 2,        c0c = tid & 3;
    const int r1c = (tid + 256) >> 2, c1c = tid & 3;

    const int niter = K / 32;

    {   // preload tile 0
        CP16(sbase + r0c*PITCH + c0c*16,            A + (size_t)(m0 + r0c)*lda + c0c*8);
        CP16(sbase + r1c*PITCH + c1c*16,            A + (size_t)(m0 + r1c)*lda + c1c*8);
        CP16(sbase + SOFF_B + r0c*PITCH + c0c*16,   B + (size_t)(n0 + r0c)*ldb + c0c*8);
        CP16(sbase + SOFF_B + r1c*PITCH + c1c*16,   B + (size_t)(n0 + r1c)*ldb + c1c*8);
        CP_COMMIT();
    }

    const int a_row = (lane & 15);
    const int a_chh = (lane >> 4);
    const int b_row = (lane & 7) + ((lane >> 4) << 3);
    const int b_chh = (lane >> 3) & 1;

    for (int i = 0; i < niter; i++) {
        const int buf = i & 1;
        if (i + 1 < niter) {
            const int k0 = (i + 1) * 32;
            const uint32_t ao = (1 - buf) * ABUF;
            CP16(sbase + ao + r0c*PITCH + c0c*16,          A + (size_t)(m0 + r0c)*lda + k0 + c0c*8);
            CP16(sbase + ao + r1c*PITCH + c1c*16,          A + (size_t)(m0 + r1c)*lda + k0 + c1c*8);
            CP16(sbase + SOFF_B + ao + r0c*PITCH + c0c*16, B + (size_t)(n0 + r0c)*ldb + k0 + c0c*8);
            CP16(sbase + SOFF_B + ao + r1c*PITCH + c1c*16, B + (size_t)(n0 + r1c)*ldb + k0 + c1c*8);
            CP_COMMIT();
            CP_WAIT1();
        } else {
            CP_WAIT0();
        }
        __syncthreads();

        const uint32_t sA = sbase + buf * ABUF;
        const uint32_t sB = sbase + SOFF_B + buf * ABUF;
        #pragma unroll
        for (int ks = 0; ks < 2; ks++) {
            uint32_t a[4][4], b[4][2];
            #pragma unroll
            for (int mi = 0; mi < 4; mi++) {
                const int row = wm*64 + mi*16 + a_row;
                const int ch  = 2*ks + a_chh;
                LDSM_X4(a[mi][0], a[mi][1], a[mi][2], a[mi][3], sA + row*PITCH + ch*16);
            }
            #pragma unroll
            for (int np = 0; np < 2; np++) {
                const int row = wn*32 + np*16 + b_row;
                const int ch  = 2*ks + b_chh;
                LDSM_X4(b[2*np][0], b[2*np][1], b[2*np+1][0], b[2*np+1][1],
                        sB + row*PITCH + ch*16);
            }
            #pragma unroll
            for (int mi = 0; mi < 4; mi++)
                #pragma unroll
                for (int nj = 0; nj < 4; nj++)
                    MMA16816(acc[mi][nj], a[mi], b[nj]);
        }
        __syncthreads();
    }

    // ---- epilogue ----
    const float rs = (EPI == 2) ? rs_ptr[0] : 0.f;
    #pragma unroll
    for (int mi = 0; mi < 4; mi++) {
        #pragma unroll
        for (int nj = 0; nj < 4; nj++) {
            const int row = m0 + wm*64 + mi*16 + (lane >> 2);
            const int col = n0 + wn*32 + nj*8 + (lane & 3)*2;
            float2 v0 = make_float2(acc[mi][nj][0], acc[mi][nj][1]);
            float2 v1 = make_float2(acc[mi][nj][2], acc[mi][nj][3]);
            if (EPI == 3) {
                if (col < RK) {
                    // bf16 dt-rank outputs
                    *(__nv_bfloat162*)(xdt + (size_t)row*RK + col) =
                        __floats2bfloat162_rn(v0.x, v0.y);
                    *(__nv_bfloat162*)(xdt + (size_t)(row+8)*RK + col) =
                        __floats2bfloat162_rn(v1.x, v1.y);
                } else if (col < Nreal) {
                    *(float2*)(C + (size_t)row*ldc + col)     = v0;
                    *(float2*)(C + (size_t)(row+8)*ldc + col) = v1;
                }
                continue;
            }
            if (EPI == 1) {
                const float b0 = aux[col], b1 = aux[col+1];
                float t;
                t = v0.x + b0; v0.x = (t > 20.f) ? t : log1pf(__expf(t));
                t = v0.y + b1; v0.y = (t > 20.f) ? t : log1pf(__expf(t));
                t = v1.x + b0; v1.x = (t > 20.f) ? t : log1pf(__expf(t));
                t = v1.y + b1; v1.y = (t > 20.f) ? t : log1pf(__expf(t));
            }
            if (EPI == 2) {
                const float2 q0 = *(const float2*)(aux + (size_t)row*ldc + col);
                const float2 q1 = *(const float2*)(aux + (size_t)(row+8)*ldc + col);
                v0.x = q0.x + rs*v0.x; v0.y = q0.y + rs*v0.y;
                v1.x = q1.x + rs*v1.x; v1.y = q1.y + rs*v1.y;
            }
            *(float2*)(C + (size_t)row*ldc + col)     = v0;
            *(float2*)(C + (size_t)(row+8)*ldc + col) = v1;
        }
    }
}

// ---------------- fp32 -> bf16 convert (with zero padding) ----------------
__global__ __launch_bounds__(256) void f2bf_pad(
    const float* __restrict__ s, __nv_bfloat16* __restrict__ d, int n_src, int n_dst)
{
    int i = blockIdx.x * 256 + threadIdx.x;
    if (i < n_dst) d[i] = (i < n_src) ? __float2bfloat16(s[i]) : __float2bfloat16(0.f);
}

// ---------------- 1) layernorm -> bf16 ----------------
__global__ __launch_bounds__(256) void ln_kernel(
    const float* __restrict__ seq, const float* __restrict__ gam,
    const float* __restrict__ bet, __nv_bfloat16* __restrict__ out)
{
    int tok = blockIdx.x;
    int tid = threadIdx.x;
    const float4 v = reinterpret_cast<const float4*>(seq + (size_t)tok*DM)[tid];
    float s = v.x + v.y + v.z + v.w;
    float q = v.x*v.x + v.y*v.y + v.z*v.z + v.w*v.w;
    #pragma unroll
    for (int o = 16; o > 0; o >>= 1) {
        s += __shfl_down_sync(0xffffffffu, s, o);
        q += __shfl_down_sync(0xffffffffu, q, o);
    }
    __shared__ float ss[8], sq[8];
    int wid = tid >> 5;
    if ((tid & 31) == 0) { ss[wid] = s; sq[wid] = q; }
    __syncthreads();
    float S = 0.f, Q = 0.f;
    #pragma unroll
    for (int i = 0; i < 8; i++) { S += ss[i]; Q += sq[i]; }
    float mu  = S * (1.f/DM);
    float var = Q * (1.f/DM) - mu*mu;
    float inv = rsqrtf(var + 1e-5f);
    const float4 g4 = reinterpret_cast<const float4*>(gam)[tid];
    const float4 b4 = reinterpret_cast<const float4*>(bet)[tid];
    float4 o4;
    o4.x = (v.x - mu)*inv*g4.x + b4.x;
    o4.y = (v.y - mu)*inv*g4.y + b4.y;
    o4.z = (v.z - mu)*inv*g4.z + b4.z;
    o4.w = (v.w - mu)*inv*g4.w + b4.w;
    __nv_bfloat162* op = reinterpret_cast<__nv_bfloat162*>(out + (size_t)tok*DM);
    op[tid*2+0] = __floats2bfloat162_rn(o4.x, o4.y);
    op[tid*2+1] = __floats2bfloat162_rn(o4.z, o4.w);
}

// ---------------- 3) causal depthwise conv + bias + SiLU (fp32 + bf16 out) --
__global__ __launch_bounds__(256) void conv_silu_kernel(
    const float* __restrict__ xz, const float* __restrict__ cw,
    const float* __restrict__ cb, float* __restrict__ out,
    __nv_bfloat16* __restrict__ out_bf)
{
    int gid = blockIdx.x * 256 + threadIdx.x;
    int t = gid / (DI/4);
    int d = (gid % (DI/4)) * 4;
    int l = t % LSEQ;

    const float4 w0 = reinterpret_cast<const float4*>(cw)[d+0];
    const float4 w1 = reinterpret_cast<const float4*>(cw)[d+1];
    const float4 w2 = reinterpret_cast<const float4*>(cw)[d+2];
    const float4 w3 = reinterpret_cast<const float4*>(cw)[d+3];
    float4 acc = reinterpret_cast<const float4*>(cb)[d >> 2];

    #pragma unroll
    for (int k = 0; k < 4; k++) {
        int ls = l + k - 3;
        if (ls >= 0) {
            const float4 xv = *reinterpret_cast<const float4*>(
                &xz[(size_t)(t + k - 3) * XZLD + d]);
            float a0 = (k==0)?w0.x:(k==1)?w0.y:(k==2)?w0.z:w0.w;
            float a1 = (k==0)?w1.x:(k==1)?w1.y:(k==2)?w1.z:w1.w;
            float a2 = (k==0)?w2.x:(k==1)?w2.y:(k==2)?w2.z:w2.w;
            float a3 = (k==0)?w3.x:(k==1)?w3.y:(k==2)?w3.z:w3.w;
            acc.x += xv.x*a0; acc.y += xv.y*a1;
            acc.z += xv.z*a2; acc.w += xv.w*a3;
        }
    }
    acc.x = siluf(acc.x); acc.y = siluf(acc.y);
    acc.z = siluf(acc.z); acc.w = siluf(acc.w);
    *reinterpret_cast<float4*>(&out[(size_t)t*DI + d]) = acc;
    __nv_bfloat162* bp = reinterpret_cast<__nv_bfloat162*>(out_bf + (size_t)t*DI + d);
    bp[0] = __floats2bfloat162_rn(acc.x, acc.y);
    bp[1] = __floats2bfloat162_rn(acc.z, acc.w);
}

// ---------------- 4) selective scan (software-pipelined) -------------------
__global__ __launch_bounds__(128) void scan_kernel(
    const float* __restrict__ dt, const float* __restrict__ xc,
    const float* __restrict__ xdbl, const float* __restrict__ xz,
    const float* __restrict__ A_log, const float* __restrict__ Dp,
    __nv_bfloat16* __restrict__ y)
{
    int warp = (blockIdx.x * 128 + threadIdx.x) >> 5;
    int lane = threadIdx.x & 31;
    int half = lane >> 4;
    int s    = lane & 15;
    int b    = warp >> 10;
    int ch   = ((warp & 1023) << 1) + half;

    float Aval = -expf(A_log[ch*DS + s]);
    float Dv   = Dp[ch];

    const float* dtp = dt   + (size_t)b*LSEQ*DI + ch;
    const float* xp  = xc   + (size_t)b*LSEQ*DI + ch;
    const float* zp  = xz   + (size_t)b*LSEQ*XZLD + DI + ch;
    const float* bp  = xdbl + (size_t)b*LSEQ*XDBL_LD + RK + s;
    const float* cp  = bp + DS;
    __nv_bfloat16* yp = y   + (size_t)b*LSEQ*DI + ch;

    // preload step 0
    float dtv = *dtp, xv = *xp, Bv = *bp, Cv = *cp, zv = *zp;

    float h = 0.f;
    for (int l = 0; l < LSEQ; l++) {
        dtp += DI; xp += DI; zp += XZLD; bp += XDBL_LD; cp += XDBL_LD;
        float ndt = 0.f, nx = 0.f, nB = 0.f, nC = 0.f, nz = 0.f;
        if (l + 1 < LSEQ) {     // prefetch next step; overlaps reduce below
            ndt = *dtp; nx = *xp; nB = *bp; nC = *cp; nz = *zp;
        }
        float dA = __expf(dtv * Aval);
        h = fmaf(h, dA, dtv * xv * Bv);
        float acc = h * Cv;
        acc += __shfl_xor_sync(0xffffffffu, acc, 1);
        acc += __shfl_xor_sync(0xffffffffu, acc, 2);
        acc += __shfl_xor_sync(0xffffffffu, acc, 4);
        acc += __shfl_xor_sync(0xffffffffu, acc, 8);
        if (s == 0) {
            yp[0] = __float2bfloat16((acc + Dv * xv) * siluf(zv));
        }
        yp += DI;
        dtv = ndt; xv = nx; Bv = nB; Cv = nC; zv = nz;
    }
}

// ---------------- launcher ----------------
extern "C" void kernel_launch(void* const* d_in, const int* in_sizes, int n_in,
                              void* d_out, int out_size)
{
    const float* seq       = (const float*)d_in[0];
    const float* ln_g      = (const float*)d_in[1];
    const float* ln_b      = (const float*)d_in[2];
    const float* in_proj_w = (const float*)d_in[3];
    const float* conv_w    = (const float*)d_in[4];
    const float* conv_b    = (const float*)d_in[5];
    const float* x_proj_w  = (const float*)d_in[6];
    const float* dt_proj_w = (const float*)d_in[7];
    const float* dt_proj_b = (const float*)d_in[8];
    const float* A_log     = (const float*)d_in[9];
    const float* Dp        = (const float*)d_in[10];
    const float* out_proj_w= (const float*)d_in[11];
    const float* res_scale = (const float*)d_in[12];
    float* out = (float*)d_out;

    __nv_bfloat16 *xn_bf, *xc_bf, *y_bf, *win_bf, *wout_bf, *wxp_bf, *wdt_bf, *xdt_bf;
    float *xz, *xc, *xdbl, *dt;
    cudaGetSymbolAddress((void**)&xn_bf,  g_xn_bf);
    cudaGetSymbolAddress((void**)&xz,     g_xz);
    cudaGetSymbolAddress((void**)&xc,     g_xc);
    cudaGetSymbolAddress((void**)&xc_bf,  g_xc_bf);
    cudaGetSymbolAddress((void**)&xdbl,   g_xdbl);
    cudaGetSymbolAddress((void**)&xdt_bf, g_xdt_bf);
    cudaGetSymbolAddress((void**)&dt,     g_dt);
    cudaGetSymbolAddress((void**)&y_bf,   g_y_bf);
    cudaGetSymbolAddress((void**)&win_bf, g_win_bf);
    cudaGetSymbolAddress((void**)&wout_bf,g_wout_bf);
    cudaGetSymbolAddress((void**)&wxp_bf, g_wxp_bf);
    cudaGetSymbolAddress((void**)&wdt_bf, g_wdt_bf);

    // 0) weight conversions to bf16
    f2bf_pad<<<(XZLD*DM + 255)/256, 256>>>(in_proj_w,  win_bf,  XZLD*DM, XZLD*DM);
    f2bf_pad<<<(DM*DI   + 255)/256, 256>>>(out_proj_w, wout_bf, DM*DI,   DM*DI);
    f2bf_pad<<<(128*DI  + 255)/256, 256>>>(x_proj_w,   wxp_bf,  XDBL_LD*DI, 128*DI);
    f2bf_pad<<<(DI*RK   + 255)/256, 256>>>(dt_proj_w,  wdt_bf,  DI*RK,   DI*RK);

    // 1) layernorm -> bf16
    ln_kernel<<<TT, 256>>>(seq, ln_g, ln_b, xn_bf);

    // 2) in_proj (HMMA): xz[4096 x 4096] = xn @ in_proj_w^T
    hgemm<0><<<dim3(XZLD/128, TT/128), 256>>>(
        xn_bf, DM, win_bf, DM, DM, xz, XZLD, XZLD, nullptr, nullptr, nullptr);

    // 3) conv + silu (fp32 + bf16 outputs)
    conv_silu_kernel<<<(TT*(DI/4))/256, 256>>>(xz, conv_w, conv_b, xc, xc_bf);

    // 4) x_proj (HMMA, N padded 96->128): cols<64 -> bf16 xdt, 64..95 -> fp32 xdbl
    hgemm<3><<<dim3(1, TT/128), 256>>>(
        xc_bf, DI, wxp_bf, DI, DI, xdbl, XDBL_LD, XDBL_LD, nullptr, nullptr, xdt_bf);

    // 5) dt = softplus(xdt @ dt_proj_w^T + b)  (HMMA, K=64)
    hgemm<1><<<dim3(DI/128, TT/128), 256>>>(
        xdt_bf, RK, wdt_bf, RK, RK, dt, DI, DI, dt_proj_b, nullptr, nullptr);

    // 6) selective scan + gating -> bf16 y
    scan_kernel<<<(BSZ*DI/2)*32/128, 128>>>(dt, xc, xdbl, xz, A_log, Dp, y_bf);

    // 7) out_proj (HMMA) + residual: out = seq + rs * (y @ out_proj_w^T)
    hgemm<2><<<dim3(DM/128, TT/128), 256>>>(
        y_bf, DI, wout_bf, DI, DI, out, DM, DM, seq, res_scale, nullptr);
}